// round 5
// baseline (speedup 1.0000x reference)
#include <cuda_runtime.h>
#include <cuda_bf16.h>
#include <mma.h>
#include <cstdint>

using namespace nvcuda;

#define BB 32768
#define CC 1024
#define CH 256

typedef __nv_bfloat16 bf16;

// ---------------- device scratch (static) ----------------
__device__ __align__(16) bf16  g_xn[(size_t)BB * CC];
__device__ __align__(16) bf16  g_dg[(size_t)BB * 512];
__device__ __align__(16) bf16  g_h1[(size_t)BB * CH];
__device__ __align__(16) bf16  g_t [(size_t)BB * CH];
__device__ __align__(16) bf16  g_h3[(size_t)BB * CH];

__device__ __align__(16) bf16  g_Wdg[1024 * 512];
__device__ __align__(16) float g_bdg[512];
__device__ __align__(16) bf16  g_W1b[256 * 256];
__device__ __align__(16) float g_Wvof[256 * 256];   // fp32 Wv@Wo
__device__ __align__(16) float g_bvo[256];
__device__ __align__(16) bf16  g_W23[256 * 256];    // W2 @ Wv @ Wo
__device__ __align__(16) float g_b23[256];
__device__ __align__(16) bf16  g_Wu2[256 * 1024];   // Wu + (Wu@Wld)@Wlu
__device__ __align__(16) float g_bu2[1024];
__device__ __align__(16) float g_T[256 * 16];

__device__ __forceinline__ float gelu_tanh(float x) {
    float x3 = x * x * x;
    return 0.5f * x * (1.0f + tanhf(0.7978845608028654f * (x + 0.044715f * x3)));
}

__device__ __forceinline__ void cp16(uint32_t d, const void* s) {
    asm volatile("cp.async.cg.shared.global [%0], [%1], 16;\n" :: "r"(d), "l"(s));
}

// ---------------- prep kernels ----------------
__global__ void cvt_kernel(const float* __restrict__ src, bf16* __restrict__ dst, int n) {
    int i = blockIdx.x * 256 + threadIdx.x;
    if (i < n) dst[i] = __float2bfloat16(src[i]);
}

__global__ void prep_wdg(const float* __restrict__ Wd, const float* __restrict__ Wg) {
    int idx = blockIdx.x * 256 + threadIdx.x;
    int k = idx >> 9, j = idx & 511;
    float v = (j < 256) ? Wd[k * 256 + j] : Wg[k * 256 + (j - 256)];
    g_Wdg[idx] = __float2bfloat16(v);
}

__global__ void prep_bdg(const float* __restrict__ bd, const float* __restrict__ bg) {
    int j = threadIdx.x;
    g_bdg[j] = (j < 256) ? bd[j] : bg[j - 256];
}

__global__ void prep_wvo(const float* __restrict__ Wv, const float* __restrict__ Wo,
                         const float* __restrict__ bv, const float* __restrict__ bo) {
    __shared__ float row[256];
    int i = blockIdx.x, j = threadIdx.x;
    row[j] = Wv[i * 256 + j];
    __syncthreads();
    float acc = 0.f;
    #pragma unroll 4
    for (int k = 0; k < 256; k++) acc += row[k] * Wo[k * 256 + j];
    g_Wvof[i * 256 + j] = acc;
    if (i == 0) {
        float b = 0.f;
        for (int k = 0; k < 256; k++) b += bv[k] * Wo[k * 256 + j];
        g_bvo[j] = b + bo[j];
    }
}

__global__ void prep_w2vo(const float* __restrict__ W2, const float* __restrict__ b2) {
    __shared__ float row[256];
    int i = blockIdx.x, j = threadIdx.x;
    row[j] = W2[i * 256 + j];
    __syncthreads();
    float acc = 0.f;
    #pragma unroll 4
    for (int k = 0; k < 256; k++) acc += row[k] * g_Wvof[k * 256 + j];
    g_W23[i * 256 + j] = __float2bfloat16(acc);
    if (i == 0) {
        float b = 0.f;
        for (int k = 0; k < 256; k++) b += b2[k] * g_Wvof[k * 256 + j];
        g_b23[j] = b + g_bvo[j];
    }
}

__global__ void prep_T(const float* __restrict__ Wu, const float* __restrict__ Wld) {
    int i = blockIdx.x, t = threadIdx.x;
    int r = t & 15, seg = t >> 4;
    float acc = 0.f;
    int k0 = seg * 64;
    #pragma unroll 4
    for (int k = k0; k < k0 + 64; k++) acc += Wu[i * 1024 + k] * Wld[k * 16 + r];
    __shared__ float red[256];
    red[t] = acc;
    __syncthreads();
    if (seg == 0) {
        float s = 0.f;
        #pragma unroll
        for (int q = 0; q < 16; q++) s += red[q * 16 + r];
        g_T[i * 16 + r] = s;
    }
}

__global__ void prep_wu2(const float* __restrict__ Wu, const float* __restrict__ Wlu) {
    int i = blockIdx.x;
    int j = blockIdx.y * 256 + threadIdx.x;
    __shared__ float Ti[16];
    if (threadIdx.x < 16) Ti[threadIdx.x] = g_T[i * 16 + threadIdx.x];
    __syncthreads();
    float acc = Wu[i * 1024 + j];
    #pragma unroll
    for (int r = 0; r < 16; r++) acc += Ti[r] * Wlu[r * 1024 + j];
    g_Wu2[i * 1024 + j] = __float2bfloat16(acc);
}

__global__ void prep_bu2(const float* __restrict__ bu, const float* __restrict__ Wld,
                         const float* __restrict__ Wlu) {
    __shared__ float s[16];
    int t = threadIdx.x;
    if (t < 16) {
        float a = 0.f;
        for (int k = 0; k < 1024; k++) a += bu[k] * Wld[k * 16 + t];
        s[t] = a;
    }
    __syncthreads();
    float acc = bu[t];
    #pragma unroll
    for (int r = 0; r < 16; r++) acc += s[r] * Wlu[r * 1024 + t];
    g_bu2[t] = acc;
}

// ---------------- LayerNorm ----------------
__global__ void ln_kernel(const float* __restrict__ x, const float* __restrict__ gw,
                          const float* __restrict__ bw) {
    int warp = threadIdx.x >> 5, lane = threadIdx.x & 31;
    int row = blockIdx.x * 8 + warp;
    const float4* xr = (const float4*)(x + (size_t)row * CC);
    float4 v[8];
    float s = 0.f, q = 0.f;
    #pragma unroll
    for (int i = 0; i < 8; i++) {
        v[i] = xr[lane + 32 * i];
        s += v[i].x + v[i].y + v[i].z + v[i].w;
        q += v[i].x * v[i].x + v[i].y * v[i].y + v[i].z * v[i].z + v[i].w * v[i].w;
    }
    #pragma unroll
    for (int o = 16; o; o >>= 1) {
        s += __shfl_xor_sync(0xffffffffu, s, o);
        q += __shfl_xor_sync(0xffffffffu, q, o);
    }
    float mu = s * (1.0f / 1024.0f);
    float var = q * (1.0f / 1024.0f) - mu * mu;
    float rs = rsqrtf(var + 1e-5f);
    uint2* dst = (uint2*)(g_xn + (size_t)row * CC);
    const float4* g4 = (const float4*)gw;
    const float4* b4 = (const float4*)bw;
    #pragma unroll
    for (int i = 0; i < 8; i++) {
        int idx = lane + 32 * i;
        float4 gg = g4[idx], bb = b4[idx];
        float y0 = (v[i].x - mu) * rs * gg.x + bb.x;
        float y1 = (v[i].y - mu) * rs * gg.y + bb.y;
        float y2 = (v[i].z - mu) * rs * gg.z + bb.z;
        float y3 = (v[i].w - mu) * rs * gg.w + bb.w;
        __nv_bfloat162 lo = __floats2bfloat162_rn(y0, y1);
        __nv_bfloat162 hi = __floats2bfloat162_rn(y2, y3);
        uint2 u;
        u.x = *reinterpret_cast<unsigned*>(&lo);
        u.y = *reinterpret_cast<unsigned*>(&hi);
        dst[idx] = u;
    }
}

// ---------------- GLU + depthwise (vectorized x4) ----------------
__global__ void glu_kernel(const float* __restrict__ dw_w, const float* __restrict__ dw_b) {
    int idx = blockIdx.x * 256 + threadIdx.x;   // < B*64
    int i = idx >> 6;
    int c = (idx & 63) << 2;
    uint2 du = *(const uint2*)(g_dg + (size_t)i * 512 + c);
    uint2 gu = *(const uint2*)(g_dg + (size_t)i * 512 + 256 + c);
    float4 wv = *(const float4*)(dw_w + c);
    float4 bv = *(const float4*)(dw_b + c);
    __nv_bfloat162 d0 = *reinterpret_cast<__nv_bfloat162*>(&du.x);
    __nv_bfloat162 d1 = *reinterpret_cast<__nv_bfloat162*>(&du.y);
    __nv_bfloat162 g0 = *reinterpret_cast<__nv_bfloat162*>(&gu.x);
    __nv_bfloat162 g1 = *reinterpret_cast<__nv_bfloat162*>(&gu.y);
    float dd[4] = {__bfloat162float(d0.x), __bfloat162float(d0.y),
                   __bfloat162float(d1.x), __bfloat162float(d1.y)};
    float gg[4] = {__bfloat162float(g0.x), __bfloat162float(g0.y),
                   __bfloat162float(g1.x), __bfloat162float(g1.y)};
    float ww[4] = {wv.x, wv.y, wv.z, wv.w};
    float bb[4] = {bv.x, bv.y, bv.z, bv.w};
    float h[4];
    #pragma unroll
    for (int q = 0; q < 4; q++) {
        float sg = 1.0f / (1.0f + __expf(-gg[q]));
        h[q] = dd[q] * sg * ww[q] + bb[q];
    }
    __nv_bfloat162 o0 = __floats2bfloat162_rn(h[0], h[1]);
    __nv_bfloat162 o1 = __floats2bfloat162_rn(h[2], h[3]);
    uint2 u;
    u.x = *reinterpret_cast<unsigned*>(&o0);
    u.y = *reinterpret_cast<unsigned*>(&o1);
    *(uint2*)(g_h1 + (size_t)i * 256 + c) = u;
}

// ---------------- pipelined smem WMMA GEMM, 128x128x32 ----------------
// EPI: 0=bias (bf16 out), 1=bias+gelu (bf16 out), 2=bias+residual mix (fp32 out)
#define AS (128 * 40)
#define BS (32 * 136)

template <int EPI, int N, int K>
__global__ void __launch_bounds__(256)
gemm_kernel(const bf16* __restrict__ A, const bf16* __restrict__ Bw,
            const float* __restrict__ bias, bf16* __restrict__ Cb,
            float* __restrict__ Cf, const float* __restrict__ xres) {
    __shared__ __align__(16) char sm[41984];
    bf16* sA = reinterpret_cast<bf16*>(sm);
    bf16* sB = reinterpret_cast<bf16*>(sm + 2 * AS * 2);
    uint32_t sA_u = (uint32_t)__cvta_generic_to_shared(sA);
    uint32_t sB_u = (uint32_t)__cvta_generic_to_shared(sB);

    int warp = threadIdx.x >> 5, lane = threadIdx.x & 31;
    int mw = warp >> 2, nw = warp & 3;
    int row0 = blockIdx.x * 128;
    int col0 = blockIdx.y * 128;

    wmma::fragment<wmma::accumulator, 16, 16, 16, float> c[4][2];
    #pragma unroll
    for (int i = 0; i < 4; i++)
        #pragma unroll
        for (int j = 0; j < 2; j++) wmma::fill_fragment(c[i][j], 0.0f);

    auto load_tile = [&](int stage, int k0) {
        #pragma unroll
        for (int i = 0; i < 2; i++) {
            int cc = threadIdx.x + i * 256;
            int ar = cc >> 2, ac = (cc & 3) << 3;
            cp16(sA_u + (stage * AS + ar * 40 + ac) * 2,
                 A + (size_t)(row0 + ar) * K + k0 + ac);
            int br = cc >> 4, bc = (cc & 15) << 3;
            cp16(sB_u + (stage * BS + br * 136 + bc) * 2,
                 Bw + (size_t)(k0 + br) * N + col0 + bc);
        }
        asm volatile("cp.async.commit_group;\n");
    };

    load_tile(0, 0);
    const int KT = K / 32;
    for (int kt = 0; kt < KT; kt++) {
        int cur = kt & 1;
        if (kt + 1 < KT) {
            load_tile(cur ^ 1, (kt + 1) * 32);
            asm volatile("cp.async.wait_group 1;\n");
        } else {
            asm volatile("cp.async.wait_group 0;\n");
        }
        __syncthreads();
        #pragma unroll
        for (int ks = 0; ks < 2; ks++) {
            wmma::fragment<wmma::matrix_a, 16, 16, 16, bf16, wmma::row_major> a[4];
            wmma::fragment<wmma::matrix_b, 16, 16, 16, bf16, wmma::row_major> b[2];
            const bf16* pa = sA + cur * AS + (mw * 64) * 40 + ks * 16;
            #pragma unroll
            for (int i = 0; i < 4; i++) wmma::load_matrix_sync(a[i], pa + i * 16 * 40, 40);
            const bf16* pb = sB + cur * BS + (ks * 16) * 136 + nw * 32;
            #pragma unroll
            for (int j = 0; j < 2; j++) wmma::load_matrix_sync(b[j], pb + j * 16, 136);
            #pragma unroll
            for (int i = 0; i < 4; i++)
                #pragma unroll
                for (int j = 0; j < 2; j++)
                    wmma::mma_sync(c[i][j], a[i], b[j], c[i][j]);
        }
        __syncthreads();
    }

    // epilogue: per-warp smem staging [64][20] floats
    float* sCw = reinterpret_cast<float*>(sm) + warp * (64 * 20);
    #pragma unroll
    for (int j = 0; j < 2; j++) {
        __syncwarp();
        #pragma unroll
        for (int i = 0; i < 4; i++)
            wmma::store_matrix_sync(sCw + i * 16 * 20, c[i][j], 20, wmma::mem_row_major);
        __syncwarp();
        int colg = (lane & 1) << 3;
        int gcol = col0 + nw * 32 + j * 16 + colg;
        float4 bv0 = *(const float4*)(bias + gcol);
        float4 bv1 = *(const float4*)(bias + gcol + 4);
        float bvv[8] = {bv0.x, bv0.y, bv0.z, bv0.w, bv1.x, bv1.y, bv1.z, bv1.w};
        #pragma unroll
        for (int it = 0; it < 4; it++) {
            int r = (lane >> 1) + it * 16;
            int grow = row0 + mw * 64 + r;
            float v[8];
            #pragma unroll
            for (int q = 0; q < 8; q++) v[q] = sCw[r * 20 + colg + q] + bvv[q];
            if (EPI == 1) {
                #pragma unroll
                for (int q = 0; q < 8; q++) v[q] = gelu_tanh(v[q]);
            }
            if (EPI == 2) {
                const float* xr = xres + (size_t)grow * N + gcol;
                float4 x0 = *(const float4*)xr;
                float4 x1 = *(const float4*)(xr + 4);
                float4 o0, o1;
                o0.x = 0.5f * v[0] + 0.5f * x0.x;
                o0.y = 0.5f * v[1] + 0.5f * x0.y;
                o0.z = 0.5f * v[2] + 0.5f * x0.z;
                o0.w = 0.5f * v[3] + 0.5f * x0.w;
                o1.x = 0.5f * v[4] + 0.5f * x1.x;
                o1.y = 0.5f * v[5] + 0.5f * x1.y;
                o1.z = 0.5f * v[6] + 0.5f * x1.z;
                o1.w = 0.5f * v[7] + 0.5f * x1.w;
                float* op = Cf + (size_t)grow * N + gcol;
                *(float4*)op = o0;
                *(float4*)(op + 4) = o1;
            } else {
                __nv_bfloat162 p0 = __floats2bfloat162_rn(v[0], v[1]);
                __nv_bfloat162 p1 = __floats2bfloat162_rn(v[2], v[3]);
                __nv_bfloat162 p2 = __floats2bfloat162_rn(v[4], v[5]);
                __nv_bfloat162 p3 = __floats2bfloat162_rn(v[6], v[7]);
                uint4 u;
                u.x = *reinterpret_cast<unsigned*>(&p0);
                u.y = *reinterpret_cast<unsigned*>(&p1);
                u.z = *reinterpret_cast<unsigned*>(&p2);
                u.w = *reinterpret_cast<unsigned*>(&p3);
                *(uint4*)(Cb + (size_t)grow * N + gcol) = u;
            }
        }
    }
}

// ---------------- launcher ----------------
extern "C" void kernel_launch(void* const* d_in, const int* in_sizes, int n_in,
                              void* d_out, int out_size) {
    const float* x    = (const float*)d_in[0];
    const float* ln_g = (const float*)d_in[1];
    const float* ln_b = (const float*)d_in[2];
    const float* Wd   = (const float*)d_in[3];
    const float* bd   = (const float*)d_in[4];
    const float* Wg   = (const float*)d_in[5];
    const float* bg   = (const float*)d_in[6];
    const float* dw_w = (const float*)d_in[7];
    const float* dw_b = (const float*)d_in[8];
    const float* W1   = (const float*)d_in[9];
    const float* b1   = (const float*)d_in[10];
    const float* W2   = (const float*)d_in[11];
    const float* b2   = (const float*)d_in[12];
    // d_in[13..16] = Wq,bq,Wk,bk : dead (softmax over single key == 1)
    const float* Wv   = (const float*)d_in[17];
    const float* bv   = (const float*)d_in[18];
    const float* Wo   = (const float*)d_in[19];
    const float* bo   = (const float*)d_in[20];
    const float* Wu   = (const float*)d_in[21];
    const float* bu   = (const float*)d_in[22];
    const float* Wld  = (const float*)d_in[23];
    const float* Wlu  = (const float*)d_in[24];
    float* out = (float*)d_out;

    // weight folding (fp32 folds, tiny)
    cvt_kernel<<<(256 * 256 + 255) / 256, 256>>>(W1, g_W1b, 256 * 256);
    prep_wdg<<<(1024 * 512) / 256, 256>>>(Wd, Wg);
    prep_bdg<<<1, 512>>>(bd, bg);
    prep_wvo<<<256, 256>>>(Wv, Wo, bv, bo);
    prep_w2vo<<<256, 256>>>(W2, b2);
    prep_T<<<256, 256>>>(Wu, Wld);
    prep_wu2<<<dim3(256, 4), 256>>>(Wu, Wlu);
    prep_bu2<<<1, 1024>>>(bu, Wld, Wlu);

    // main pipeline
    ln_kernel<<<BB / 8, 256>>>(x, ln_g, ln_b);
    gemm_kernel<0, 512, 1024><<<dim3(BB / 128, 4), 256>>>(g_xn, g_Wdg, g_bdg, g_dg, nullptr, nullptr);
    glu_kernel<<<(BB * 64) / 256, 256>>>(dw_w, dw_b);
    gemm_kernel<1, 256, 256><<<dim3(BB / 128, 2), 256>>>(g_h1, g_W1b, b1, g_t, nullptr, nullptr);
    gemm_kernel<0, 256, 256><<<dim3(BB / 128, 2), 256>>>(g_t, g_W23, g_b23, g_h3, nullptr, nullptr);
    gemm_kernel<2, 1024, 256><<<dim3(BB / 128, 8), 256>>>(g_h3, g_Wu2, g_bu2, nullptr, out, x);
}

// round 6
// speedup vs baseline: 8.8016x; 8.8016x over previous
#include <cuda_runtime.h>
#include <cuda_bf16.h>
#include <mma.h>
#include <cstdint>

using namespace nvcuda;

#define BB 32768
#define CC 1024
#define CH 256

typedef __nv_bfloat16 bf16;

// ---------------- device scratch (static, no allocation) ----------------
__device__ __align__(16) bf16  g_xn[(size_t)BB * CC];        // LN output, bf16
__device__ __align__(16) bf16  g_dg[(size_t)BB * 512];       // [d | g] pre-GLU
__device__ __align__(16) bf16  g_h1[(size_t)BB * CH];
__device__ __align__(16) bf16  g_t [(size_t)BB * CH];
__device__ __align__(16) bf16  g_h3[(size_t)BB * CH];

__device__ __align__(16) bf16  g_Wdg[1024 * 512];            // [Wd | Wg] bf16
__device__ __align__(16) float g_bdg[512];
__device__ __align__(16) bf16  g_W1b[256 * 256];
__device__ __align__(16) float g_Wvof[256 * 256];            // fp32 Wv@Wo
__device__ __align__(16) float g_bvo[256];
__device__ __align__(16) bf16  g_W23[256 * 256];             // W2 @ (Wv@Wo)
__device__ __align__(16) float g_b23[256];
__device__ __align__(16) bf16  g_Wu2[256 * 1024];            // Wu + (Wu@Wld)@Wlu
__device__ __align__(16) float g_bu2[1024];
__device__ __align__(16) float g_T[256 * 16];

// ---------------- helpers ----------------
__device__ __forceinline__ float gelu_tanh(float x) {
    float x3 = x * x * x;
    return 0.5f * x * (1.0f + tanhf(0.7978845608028654f * (x + 0.044715f * x3)));
}

// ---------------- prep kernels ----------------
__global__ void cvt_kernel(const float* __restrict__ src, bf16* __restrict__ dst, int n) {
    int i = blockIdx.x * 256 + threadIdx.x;
    if (i < n) dst[i] = __float2bfloat16(src[i]);
}

__global__ void prep_wdg(const float* __restrict__ Wd, const float* __restrict__ Wg) {
    int idx = blockIdx.x * 256 + threadIdx.x;   // < 1024*512
    int k = idx >> 9, j = idx & 511;
    float v = (j < 256) ? Wd[k * 256 + j] : Wg[k * 256 + (j - 256)];
    g_Wdg[idx] = __float2bfloat16(v);
}

__global__ void prep_bdg(const float* __restrict__ bd, const float* __restrict__ bg) {
    int j = threadIdx.x;  // 512 threads
    g_bdg[j] = (j < 256) ? bd[j] : bg[j - 256];
}

// Wvo = Wv @ Wo (fp32), bvo = bv @ Wo + bo. 4-way ILP accumulators.
__global__ void prep_wvo(const float* __restrict__ Wv, const float* __restrict__ Wo,
                         const float* __restrict__ bv, const float* __restrict__ bo) {
    __shared__ float row[256];
    int i = blockIdx.x, j = threadIdx.x;
    row[j] = Wv[i * 256 + j];
    __syncthreads();
    float a0 = 0.f, a1 = 0.f, a2 = 0.f, a3 = 0.f;
    #pragma unroll 4
    for (int k = 0; k < 256; k += 4) {
        a0 += row[k + 0] * Wo[(k + 0) * 256 + j];
        a1 += row[k + 1] * Wo[(k + 1) * 256 + j];
        a2 += row[k + 2] * Wo[(k + 2) * 256 + j];
        a3 += row[k + 3] * Wo[(k + 3) * 256 + j];
    }
    g_Wvof[i * 256 + j] = (a0 + a1) + (a2 + a3);
    if (i == 0) {
        float b0 = 0.f, b1_ = 0.f;
        for (int k = 0; k < 256; k += 2) {
            b0  += bv[k] * Wo[k * 256 + j];
            b1_ += bv[k + 1] * Wo[(k + 1) * 256 + j];
        }
        g_bvo[j] = b0 + b1_ + bo[j];
    }
}

// W23 = W2 @ Wvo, b23 = b2 @ Wvo + bvo
__global__ void prep_w2vo(const float* __restrict__ W2, const float* __restrict__ b2) {
    __shared__ float row[256];
    int i = blockIdx.x, j = threadIdx.x;
    row[j] = W2[i * 256 + j];
    __syncthreads();
    float a0 = 0.f, a1 = 0.f, a2 = 0.f, a3 = 0.f;
    #pragma unroll 4
    for (int k = 0; k < 256; k += 4) {
        a0 += row[k + 0] * g_Wvof[(k + 0) * 256 + j];
        a1 += row[k + 1] * g_Wvof[(k + 1) * 256 + j];
        a2 += row[k + 2] * g_Wvof[(k + 2) * 256 + j];
        a3 += row[k + 3] * g_Wvof[(k + 3) * 256 + j];
    }
    g_W23[i * 256 + j] = __float2bfloat16((a0 + a1) + (a2 + a3));
    if (i == 0) {
        float b0 = 0.f, b1_ = 0.f;
        for (int k = 0; k < 256; k += 2) {
            b0  += b2[k] * g_Wvof[k * 256 + j];
            b1_ += b2[k + 1] * g_Wvof[(k + 1) * 256 + j];
        }
        g_b23[j] = b0 + b1_ + g_bvo[j];
    }
}

__global__ void prep_T(const float* __restrict__ Wu, const float* __restrict__ Wld) {
    int i = blockIdx.x, t = threadIdx.x;      // 256 threads
    int r = t & 15, seg = t >> 4;
    float acc = 0.f;
    int k0 = seg * 64;
    #pragma unroll 4
    for (int k = k0; k < k0 + 64; k++) acc += Wu[i * 1024 + k] * Wld[k * 16 + r];
    __shared__ float red[256];
    red[t] = acc;
    __syncthreads();
    if (seg == 0) {
        float s = 0.f;
        #pragma unroll
        for (int q = 0; q < 16; q++) s += red[q * 16 + r];
        g_T[i * 16 + r] = s;
    }
}

__global__ void prep_wu2(const float* __restrict__ Wu, const float* __restrict__ Wlu) {
    int i = blockIdx.x;
    int j = blockIdx.y * 256 + threadIdx.x;
    __shared__ float Ti[16];
    if (threadIdx.x < 16) Ti[threadIdx.x] = g_T[i * 16 + threadIdx.x];
    __syncthreads();
    float acc = Wu[i * 1024 + j];
    #pragma unroll
    for (int r = 0; r < 16; r++) acc += Ti[r] * Wlu[r * 1024 + j];
    g_Wu2[i * 1024 + j] = __float2bfloat16(acc);
}

__global__ void prep_bu2(const float* __restrict__ bu, const float* __restrict__ Wld,
                         const float* __restrict__ Wlu) {
    __shared__ float s[16];
    int t = threadIdx.x;  // 1024 threads
    if (t < 16) {
        float a = 0.f;
        for (int k = 0; k < 1024; k++) a += bu[k] * Wld[k * 16 + t];
        s[t] = a;
    }
    __syncthreads();
    float acc = bu[t];
    #pragma unroll
    for (int r = 0; r < 16; r++) acc += s[r] * Wlu[r * 1024 + t];
    g_bu2[t] = acc;
}

// ---------------- LayerNorm: one warp per row ----------------
__global__ void ln_kernel(const float* __restrict__ x, const float* __restrict__ gw,
                          const float* __restrict__ bw) {
    int warp = threadIdx.x >> 5, lane = threadIdx.x & 31;
    int row = blockIdx.x * 8 + warp;
    const float4* xr = (const float4*)(x + (size_t)row * CC);
    float4 v[8];
    float s = 0.f, q = 0.f;
    #pragma unroll
    for (int i = 0; i < 8; i++) {
        v[i] = xr[lane + 32 * i];
        s += v[i].x + v[i].y + v[i].z + v[i].w;
        q += v[i].x * v[i].x + v[i].y * v[i].y + v[i].z * v[i].z + v[i].w * v[i].w;
    }
    #pragma unroll
    for (int o = 16; o; o >>= 1) {
        s += __shfl_xor_sync(0xffffffffu, s, o);
        q += __shfl_xor_sync(0xffffffffu, q, o);
    }
    float mu = s * (1.0f / 1024.0f);
    float var = q * (1.0f / 1024.0f) - mu * mu;
    float rs = rsqrtf(var + 1e-5f);
    uint2* dst = (uint2*)(g_xn + (size_t)row * CC);
    const float4* g4 = (const float4*)gw;
    const float4* b4 = (const float4*)bw;
    #pragma unroll
    for (int i = 0; i < 8; i++) {
        int idx = lane + 32 * i;
        float4 gg = g4[idx], bb = b4[idx];
        float y0 = (v[i].x - mu) * rs * gg.x + bb.x;
        float y1 = (v[i].y - mu) * rs * gg.y + bb.y;
        float y2 = (v[i].z - mu) * rs * gg.z + bb.z;
        float y3 = (v[i].w - mu) * rs * gg.w + bb.w;
        __nv_bfloat162 lo = __floats2bfloat162_rn(y0, y1);
        __nv_bfloat162 hi = __floats2bfloat162_rn(y2, y3);
        uint2 u;
        u.x = *reinterpret_cast<unsigned*>(&lo);
        u.y = *reinterpret_cast<unsigned*>(&hi);
        dst[idx] = u;
    }
}

// ---------------- GLU + depthwise (vectorized x4) ----------------
__global__ void glu_kernel(const float* __restrict__ dw_w, const float* __restrict__ dw_b) {
    int idx = blockIdx.x * 256 + threadIdx.x;   // < B*64
    int i = idx >> 6;
    int c = (idx & 63) << 2;
    uint2 du = *(const uint2*)(g_dg + (size_t)i * 512 + c);
    uint2 gu = *(const uint2*)(g_dg + (size_t)i * 512 + 256 + c);
    float4 wv = *(const float4*)(dw_w + c);
    float4 bv = *(const float4*)(dw_b + c);
    __nv_bfloat162 d0 = *reinterpret_cast<__nv_bfloat162*>(&du.x);
    __nv_bfloat162 d1 = *reinterpret_cast<__nv_bfloat162*>(&du.y);
    __nv_bfloat162 g0 = *reinterpret_cast<__nv_bfloat162*>(&gu.x);
    __nv_bfloat162 g1 = *reinterpret_cast<__nv_bfloat162*>(&gu.y);
    float dd[4] = {__bfloat162float(d0.x), __bfloat162float(d0.y),
                   __bfloat162float(d1.x), __bfloat162float(d1.y)};
    float gg[4] = {__bfloat162float(g0.x), __bfloat162float(g0.y),
                   __bfloat162float(g1.x), __bfloat162float(g1.y)};
    float ww[4] = {wv.x, wv.y, wv.z, wv.w};
    float bb[4] = {bv.x, bv.y, bv.z, bv.w};
    float h[4];
    #pragma unroll
    for (int q = 0; q < 4; q++) {
        float sg = 1.0f / (1.0f + __expf(-gg[q]));
        h[q] = dd[q] * sg * ww[q] + bb[q];
    }
    __nv_bfloat162 o0 = __floats2bfloat162_rn(h[0], h[1]);
    __nv_bfloat162 o1 = __floats2bfloat162_rn(h[2], h[3]);
    uint2 u;
    u.x = *reinterpret_cast<unsigned*>(&o0);
    u.y = *reinterpret_cast<unsigned*>(&o1);
    *(uint2*)(g_h1 + (size_t)i * 256 + c) = u;
}

// ---------------- direct-WMMA GEMM (R2-proven body), 64x128 block tile ----------------
// Grid: (N/128, BB/64) — column tile is blockIdx.x (fastest) so concurrent CTAs
// share the same A row-tile -> A is read from DRAM once, re-reads hit L2.
// EPI: 0 = bias (bf16 out), 1 = bias + gelu (bf16 out), 2 = bias + residual mix (fp32 out)
template <int EPI, int N, int K>
__device__ __forceinline__ void gemm_body(const bf16* __restrict__ A,
                                          const bf16* __restrict__ Bw,
                                          const float* __restrict__ bias,
                                          bf16* __restrict__ Cb,
                                          float* __restrict__ Cf,
                                          const float* __restrict__ xres) {
    __shared__ float sC[64 * 132];
    int warp = threadIdx.x >> 5;
    int mw = warp >> 2, nw = warp & 3;                // 2 x 4 warp grid
    int row0 = blockIdx.y * 64 + mw * 32;
    int col0 = blockIdx.x * 128 + nw * 32;

    wmma::fragment<wmma::accumulator, 16, 16, 16, float> c[2][2];
    #pragma unroll
    for (int i = 0; i < 2; i++)
        #pragma unroll
        for (int j = 0; j < 2; j++) wmma::fill_fragment(c[i][j], 0.0f);

    const bf16* Aptr = A + (size_t)row0 * K;
    #pragma unroll 4
    for (int k = 0; k < K; k += 16) {
        wmma::fragment<wmma::matrix_a, 16, 16, 16, bf16, wmma::row_major> a0, a1;
        wmma::fragment<wmma::matrix_b, 16, 16, 16, bf16, wmma::row_major> b0, b1;
        wmma::load_matrix_sync(a0, Aptr + k, K);
        wmma::load_matrix_sync(a1, Aptr + (size_t)16 * K + k, K);
        wmma::load_matrix_sync(b0, Bw + (size_t)k * N + col0, N);
        wmma::load_matrix_sync(b1, Bw + (size_t)k * N + col0 + 16, N);
        wmma::mma_sync(c[0][0], a0, b0, c[0][0]);
        wmma::mma_sync(c[0][1], a0, b1, c[0][1]);
        wmma::mma_sync(c[1][0], a1, b0, c[1][0]);
        wmma::mma_sync(c[1][1], a1, b1, c[1][1]);
    }

    #pragma unroll
    for (int i = 0; i < 2; i++)
        #pragma unroll
        for (int j = 0; j < 2; j++)
            wmma::store_matrix_sync(sC + (mw * 32 + 16 * i) * 132 + nw * 32 + 16 * j,
                                    c[i][j], 132, wmma::mem_row_major);
    __syncthreads();

    #pragma unroll
    for (int e = threadIdx.x; e < 64 * 32; e += 256) {
        int r = e >> 5;
        int c4 = (e & 31) << 2;
        int grow = blockIdx.y * 64 + r;
        int gcol = blockIdx.x * 128 + c4;
        float4 bv = *(const float4*)(bias + gcol);
        float v0 = sC[r * 132 + c4 + 0] + bv.x;
        float v1 = sC[r * 132 + c4 + 1] + bv.y;
        float v2 = sC[r * 132 + c4 + 2] + bv.z;
        float v3 = sC[r * 132 + c4 + 3] + bv.w;
        if (EPI == 1) {
            v0 = gelu_tanh(v0); v1 = gelu_tanh(v1);
            v2 = gelu_tanh(v2); v3 = gelu_tanh(v3);
        }
        if (EPI == 2) {
            float4 xv = *(const float4*)(xres + (size_t)grow * N + gcol);
            float4 o;
            o.x = 0.5f * v0 + 0.5f * xv.x;
            o.y = 0.5f * v1 + 0.5f * xv.y;
            o.z = 0.5f * v2 + 0.5f * xv.z;
            o.w = 0.5f * v3 + 0.5f * xv.w;
            *(float4*)(Cf + (size_t)grow * N + gcol) = o;
        } else {
            __nv_bfloat162 lo = __floats2bfloat162_rn(v0, v1);
            __nv_bfloat162 hi = __floats2bfloat162_rn(v2, v3);
            uint2 u;
            u.x = *reinterpret_cast<unsigned*>(&lo);
            u.y = *reinterpret_cast<unsigned*>(&hi);
            *(uint2*)(Cb + (size_t)grow * N + gcol) = u;
        }
    }
}

__global__ void gemm1_kernel() {                                      // xn @ [Wd|Wg]
    gemm_body<0, 512, 1024>(g_xn, g_Wdg, g_bdg, g_dg, nullptr, nullptr);
}
__global__ void gemm2_kernel(const float* __restrict__ b1) {          // gelu(h1@W1+b1)
    gemm_body<1, 256, 256>(g_h1, g_W1b, b1, g_t, nullptr, nullptr);
}
__global__ void gemm3_kernel() {                                      // t@W23+b23 (folded W2,Wv,Wo)
    gemm_body<0, 256, 256>(g_t, g_W23, g_b23, g_h3, nullptr, nullptr);
}
__global__ void gemm5_kernel(float* __restrict__ out, const float* __restrict__ x) {
    gemm_body<2, 1024, 256>(g_h3, g_Wu2, g_bu2, nullptr, out, x);     // up-proj + mix
}

// ---------------- launcher ----------------
// Launch order puts gemm1 at position 6 so ncu's "-s 5 -c 1" captures it.
extern "C" void kernel_launch(void* const* d_in, const int* in_sizes, int n_in,
                              void* d_out, int out_size) {
    const float* x    = (const float*)d_in[0];
    const float* ln_g = (const float*)d_in[1];
    const float* ln_b = (const float*)d_in[2];
    const float* Wd   = (const float*)d_in[3];
    const float* bd   = (const float*)d_in[4];
    const float* Wg   = (const float*)d_in[5];
    const float* bg   = (const float*)d_in[6];
    const float* dw_w = (const float*)d_in[7];
    const float* dw_b = (const float*)d_in[8];
    const float* W1   = (const float*)d_in[9];
    const float* b1   = (const float*)d_in[10];
    const float* W2   = (const float*)d_in[11];
    const float* b2   = (const float*)d_in[12];
    // d_in[13..16] = Wq,bq,Wk,bk : dead (softmax over a single key == 1)
    const float* Wv   = (const float*)d_in[17];
    const float* bv   = (const float*)d_in[18];
    const float* Wo   = (const float*)d_in[19];
    const float* bo   = (const float*)d_in[20];
    const float* Wu   = (const float*)d_in[21];
    const float* bu   = (const float*)d_in[22];
    const float* Wld  = (const float*)d_in[23];
    const float* Wlu  = (const float*)d_in[24];
    float* out = (float*)d_out;

    // 1-5: preps needed before gemm1, plus ln
    prep_wdg<<<(1024 * 512) / 256, 256>>>(Wd, Wg);                    // 1
    prep_bdg<<<1, 512>>>(bd, bg);                                     // 2
    cvt_kernel<<<(256 * 256 + 255) / 256, 256>>>(W1, g_W1b, 256*256); // 3
    prep_wvo<<<256, 256>>>(Wv, Wo, bv, bo);                           // 4
    ln_kernel<<<BB / 8, 256>>>(x, ln_g, ln_b);                        // 5
    // 6: the big one (ncu target)
    gemm1_kernel<<<dim3(512 / 128, BB / 64), 256>>>();                // 6
    glu_kernel<<<(BB * 64) / 256, 256>>>(dw_w, dw_b);                 // 7
    prep_w2vo<<<256, 256>>>(W2, b2);                                  // 8
    gemm2_kernel<<<dim3(256 / 128, BB / 64), 256>>>(b1);              // 9
    gemm3_kernel<<<dim3(256 / 128, BB / 64), 256>>>();                // 10
    prep_T<<<256, 256>>>(Wu, Wld);                                    // 11
    prep_wu2<<<dim3(256, 4), 256>>>(Wu, Wlu);                         // 12
    prep_bu2<<<1, 1024>>>(bu, Wld, Wlu);                              // 13
    gemm5_kernel<<<dim3(1024 / 128, BB / 64), 256>>>(out, x);         // 14
}

// round 8
// speedup vs baseline: 9.2850x; 1.0549x over previous
#include <cuda_runtime.h>
#include <cuda_bf16.h>
#include <mma.h>
#include <cstdint>

using namespace nvcuda;

#define BB 32768
#define CC 1024
#define CH 256

typedef __nv_bfloat16 bf16;

// ---------------- device scratch (static, no allocation) ----------------
__device__ __align__(16) bf16  g_xn[(size_t)BB * CC];        // LN output, bf16
__device__ __align__(16) bf16  g_h1[(size_t)BB * CH];
__device__ __align__(16) bf16  g_t [(size_t)BB * CH];
__device__ __align__(16) bf16  g_h3[(size_t)BB * CH];

__device__ __align__(16) bf16  g_Wdg[1024 * 512];            // [Wd | Wg] bf16
__device__ __align__(16) float g_bdg[512];
__device__ __align__(16) bf16  g_W1b[256 * 256];
__device__ __align__(16) float g_Wvof[256 * 256];            // fp32 Wv@Wo
__device__ __align__(16) float g_bvo[256];
__device__ __align__(16) bf16  g_W23[256 * 256];             // W2 @ (Wv@Wo)
__device__ __align__(16) float g_b23[256];
__device__ __align__(16) bf16  g_Wu2[256 * 1024];            // Wu + (Wu@Wld)@Wlu
__device__ __align__(16) float g_bu2[1024];
__device__ __align__(16) float g_T[256 * 16];

// ---------------- helpers ----------------
__device__ __forceinline__ float gelu_tanh(float x) {
    float x3 = x * x * x;
    return 0.5f * x * (1.0f + tanhf(0.7978845608028654f * (x + 0.044715f * x3)));
}

__device__ __forceinline__ void cp16(uint32_t d, const void* s) {
    asm volatile("cp.async.cg.shared.global [%0], [%1], 16;\n" :: "r"(d), "l"(s));
}

// ---------------- prep kernels ----------------
__global__ void cvt_kernel(const float* __restrict__ src, bf16* __restrict__ dst, int n) {
    int i = blockIdx.x * 256 + threadIdx.x;
    if (i < n) dst[i] = __float2bfloat16(src[i]);
}

__global__ void prep_wdg(const float* __restrict__ Wd, const float* __restrict__ Wg) {
    int idx = blockIdx.x * 256 + threadIdx.x;   // < 1024*512
    int k = idx >> 9, j = idx & 511;
    float v = (j < 256) ? Wd[k * 256 + j] : Wg[k * 256 + (j - 256)];
    g_Wdg[idx] = __float2bfloat16(v);
}

__global__ void prep_bdg(const float* __restrict__ bd, const float* __restrict__ bg) {
    int j = threadIdx.x;  // 512 threads
    g_bdg[j] = (j < 256) ? bd[j] : bg[j - 256];
}

__global__ void prep_wvo(const float* __restrict__ Wv, const float* __restrict__ Wo,
                         const float* __restrict__ bv, const float* __restrict__ bo) {
    __shared__ float row[256];
    int i = blockIdx.x, j = threadIdx.x;
    row[j] = Wv[i * 256 + j];
    __syncthreads();
    float a0 = 0.f, a1 = 0.f, a2 = 0.f, a3 = 0.f;
    #pragma unroll 4
    for (int k = 0; k < 256; k += 4) {
        a0 += row[k + 0] * Wo[(k + 0) * 256 + j];
        a1 += row[k + 1] * Wo[(k + 1) * 256 + j];
        a2 += row[k + 2] * Wo[(k + 2) * 256 + j];
        a3 += row[k + 3] * Wo[(k + 3) * 256 + j];
    }
    g_Wvof[i * 256 + j] = (a0 + a1) + (a2 + a3);
    if (i == 0) {
        float b0 = 0.f, b1_ = 0.f;
        for (int k = 0; k < 256; k += 2) {
            b0  += bv[k] * Wo[k * 256 + j];
            b1_ += bv[k + 1] * Wo[(k + 1) * 256 + j];
        }
        g_bvo[j] = b0 + b1_ + bo[j];
    }
}

__global__ void prep_w2vo(const float* __restrict__ W2, const float* __restrict__ b2) {
    __shared__ float row[256];
    int i = blockIdx.x, j = threadIdx.x;
    row[j] = W2[i * 256 + j];
    __syncthreads();
    float a0 = 0.f, a1 = 0.f, a2 = 0.f, a3 = 0.f;
    #pragma unroll 4
    for (int k = 0; k < 256; k += 4) {
        a0 += row[k + 0] * g_Wvof[(k + 0) * 256 + j];
        a1 += row[k + 1] * g_Wvof[(k + 1) * 256 + j];
        a2 += row[k + 2] * g_Wvof[(k + 2) * 256 + j];
        a3 += row[k + 3] * g_Wvof[(k + 3) * 256 + j];
    }
    g_W23[i * 256 + j] = __float2bfloat16((a0 + a1) + (a2 + a3));
    if (i == 0) {
        float b0 = 0.f, b1_ = 0.f;
        for (int k = 0; k < 256; k += 2) {
            b0  += b2[k] * g_Wvof[k * 256 + j];
            b1_ += b2[k + 1] * g_Wvof[(k + 1) * 256 + j];
        }
        g_b23[j] = b0 + b1_ + g_bvo[j];
    }
}

__global__ void prep_T(const float* __restrict__ Wu, const float* __restrict__ Wld) {
    int i = blockIdx.x, t = threadIdx.x;
    int r = t & 15, seg = t >> 4;
    float acc = 0.f;
    int k0 = seg * 64;
    #pragma unroll 4
    for (int k = k0; k < k0 + 64; k++) acc += Wu[i * 1024 + k] * Wld[k * 16 + r];
    __shared__ float red[256];
    red[t] = acc;
    __syncthreads();
    if (seg == 0) {
        float s = 0.f;
        #pragma unroll
        for (int q = 0; q < 16; q++) s += red[q * 16 + r];
        g_T[i * 16 + r] = s;
    }
}

__global__ void prep_wu2(const float* __restrict__ Wu, const float* __restrict__ Wlu) {
    int i = blockIdx.x;
    int j = blockIdx.y * 256 + threadIdx.x;
    __shared__ float Ti[16];
    if (threadIdx.x < 16) Ti[threadIdx.x] = g_T[i * 16 + threadIdx.x];
    __syncthreads();
    float acc = Wu[i * 1024 + j];
    #pragma unroll
    for (int r = 0; r < 16; r++) acc += Ti[r] * Wlu[r * 1024 + j];
    g_Wu2[i * 1024 + j] = __float2bfloat16(acc);
}

__global__ void prep_bu2(const float* __restrict__ bu, const float* __restrict__ Wld,
                         const float* __restrict__ Wlu) {
    __shared__ float s[16];
    int t = threadIdx.x;
    if (t < 16) {
        float a = 0.f;
        for (int k = 0; k < 1024; k++) a += bu[k] * Wld[k * 16 + t];
        s[t] = a;
    }
    __syncthreads();
    float acc = bu[t];
    #pragma unroll
    for (int r = 0; r < 16; r++) acc += s[r] * Wlu[r * 1024 + t];
    g_bu2[t] = acc;
}

// ---------------- LayerNorm: one warp per row ----------------
__global__ void ln_kernel(const float* __restrict__ x, const float* __restrict__ gw,
                          const float* __restrict__ bw) {
    int warp = threadIdx.x >> 5, lane = threadIdx.x & 31;
    int row = blockIdx.x * 8 + warp;
    const float4* xr = (const float4*)(x + (size_t)row * CC);
    float4 v[8];
    float s = 0.f, q = 0.f;
    #pragma unroll
    for (int i = 0; i < 8; i++) {
        v[i] = xr[lane + 32 * i];
        s += v[i].x + v[i].y + v[i].z + v[i].w;
        q += v[i].x * v[i].x + v[i].y * v[i].y + v[i].z * v[i].z + v[i].w * v[i].w;
    }
    #pragma unroll
    for (int o = 16; o; o >>= 1) {
        s += __shfl_xor_sync(0xffffffffu, s, o);
        q += __shfl_xor_sync(0xffffffffu, q, o);
    }
    float mu = s * (1.0f / 1024.0f);
    float var = q * (1.0f / 1024.0f) - mu * mu;
    float rs = rsqrtf(var + 1e-5f);
    uint2* dst = (uint2*)(g_xn + (size_t)row * CC);
    const float4* g4 = (const float4*)gw;
    const float4* b4 = (const float4*)bw;
    #pragma unroll
    for (int i = 0; i < 8; i++) {
        int idx = lane + 32 * i;
        float4 gg = g4[idx], bb = b4[idx];
        float y0 = (v[i].x - mu) * rs * gg.x + bb.x;
        float y1 = (v[i].y - mu) * rs * gg.y + bb.y;
        float y2 = (v[i].z - mu) * rs * gg.z + bb.z;
        float y3 = (v[i].w - mu) * rs * gg.w + bb.w;
        __nv_bfloat162 lo = __floats2bfloat162_rn(y0, y1);
        __nv_bfloat162 hi = __floats2bfloat162_rn(y2, y3);
        uint2 u;
        u.x = *reinterpret_cast<unsigned*>(&lo);
        u.y = *reinterpret_cast<unsigned*>(&hi);
        dst[idx] = u;
    }
}

// ---------------- gemm1 fused with GLU + depthwise affine ----------------
// CTA: 64 rows x (64 d-cols + 64 g-cols). Warps nw<2 -> d half, nw>=2 -> g half.
// Same per-warp register shape as the proven R2 body (c[2][2]).
__global__ void __launch_bounds__(256)
gemm1_glu_kernel(const float* __restrict__ dw_w, const float* __restrict__ dw_b) {
    __shared__ float sC[64 * 132];
    int warp = threadIdx.x >> 5;
    int mw = warp >> 2, nw = warp & 3;
    int row0 = blockIdx.y * 64 + mw * 32;
    int base = blockIdx.x * 64;                       // d-col base (0..192)
    int col0 = (nw < 2) ? (base + nw * 32) : (256 + base + (nw - 2) * 32);

    wmma::fragment<wmma::accumulator, 16, 16, 16, float> c[2][2];
    #pragma unroll
    for (int i = 0; i < 2; i++)
        #pragma unroll
        for (int j = 0; j < 2; j++) wmma::fill_fragment(c[i][j], 0.0f);

    const bf16* Aptr = g_xn + (size_t)row0 * 1024;
    #pragma unroll 4
    for (int k = 0; k < 1024; k += 16) {
        wmma::fragment<wmma::matrix_a, 16, 16, 16, bf16, wmma::row_major> a0, a1;
        wmma::fragment<wmma::matrix_b, 16, 16, 16, bf16, wmma::row_major> b0, b1;
        wmma::load_matrix_sync(a0, Aptr + k, 1024);
        wmma::load_matrix_sync(a1, Aptr + (size_t)16 * 1024 + k, 1024);
        wmma::load_matrix_sync(b0, g_Wdg + (size_t)k * 512 + col0, 512);
        wmma::load_matrix_sync(b1, g_Wdg + (size_t)k * 512 + col0 + 16, 512);
        wmma::mma_sync(c[0][0], a0, b0, c[0][0]);
        wmma::mma_sync(c[0][1], a0, b1, c[0][1]);
        wmma::mma_sync(c[1][0], a1, b0, c[1][0]);
        wmma::mma_sync(c[1][1], a1, b1, c[1][1]);
    }

    int scol = (nw < 2) ? nw * 32 : 64 + (nw - 2) * 32;   // d at [0,64), g at [64,128)
    #pragma unroll
    for (int i = 0; i < 2; i++)
        #pragma unroll
        for (int j = 0; j < 2; j++)
            wmma::store_matrix_sync(sC + (mw * 32 + 16 * i) * 132 + scol + 16 * j,
                                    c[i][j], 132, wmma::mem_row_major);
    __syncthreads();

    int rowb = blockIdx.y * 64;
    #pragma unroll
    for (int e = threadIdx.x; e < 64 * 16; e += 256) {
        int r = e >> 4;
        int c4 = (e & 15) << 2;
        int gcol = base + c4;
        float4 bd4 = *(const float4*)(g_bdg + gcol);
        float4 bg4 = *(const float4*)(g_bdg + 256 + gcol);
        float4 w4  = *(const float4*)(dw_w + gcol);
        float4 bb4 = *(const float4*)(dw_b + gcol);
        float d0 = sC[r * 132 + c4 + 0] + bd4.x;
        float d1 = sC[r * 132 + c4 + 1] + bd4.y;
        float d2 = sC[r * 132 + c4 + 2] + bd4.z;
        float d3 = sC[r * 132 + c4 + 3] + bd4.w;
        float q0 = sC[r * 132 + 64 + c4 + 0] + bg4.x;
        float q1 = sC[r * 132 + 64 + c4 + 1] + bg4.y;
        float q2 = sC[r * 132 + 64 + c4 + 2] + bg4.z;
        float q3 = sC[r * 132 + 64 + c4 + 3] + bg4.w;
        float h0 = d0 * (1.0f / (1.0f + __expf(-q0))) * w4.x + bb4.x;
        float h1 = d1 * (1.0f / (1.0f + __expf(-q1))) * w4.y + bb4.y;
        float h2 = d2 * (1.0f / (1.0f + __expf(-q2))) * w4.z + bb4.z;
        float h3 = d3 * (1.0f / (1.0f + __expf(-q3))) * w4.w + bb4.w;
        __nv_bfloat162 lo = __floats2bfloat162_rn(h0, h1);
        __nv_bfloat162 hi = __floats2bfloat162_rn(h2, h3);
        uint2 u;
        u.x = *reinterpret_cast<unsigned*>(&lo);
        u.y = *reinterpret_cast<unsigned*>(&hi);
        *(uint2*)(g_h1 + (size_t)(rowb + r) * 256 + gcol) = u;
    }
}

// ---------------- EXPERIMENT: smem-pipelined gemm2 (low register pressure) ------
// 512 threads, CTA 128x128, 4x4 warps each 32x32 (c[2][2] only), cp.async 2-stage.
#define AS2 5120    // 128 * 40 elements per A stage
#define BS2 4352    // 32 * 136 elements per B stage

__global__ void __launch_bounds__(512)
gemm2s_kernel(const float* __restrict__ b1) {
    __shared__ __align__(16) char sm[37888];
    bf16* sA = reinterpret_cast<bf16*>(sm);
    bf16* sB = reinterpret_cast<bf16*>(sm + 2 * AS2 * 2);
    uint32_t sA_u = (uint32_t)__cvta_generic_to_shared(sA);
    uint32_t sB_u = (uint32_t)__cvta_generic_to_shared(sB);

    int tid = threadIdx.x;
    int warp = tid >> 5, lane = tid & 31;
    int mw = warp >> 2, nw = warp & 3;
    int row0 = blockIdx.y * 128;
    int col0 = blockIdx.x * 128;

    wmma::fragment<wmma::accumulator, 16, 16, 16, float> c[2][2];
    #pragma unroll
    for (int i = 0; i < 2; i++)
        #pragma unroll
        for (int j = 0; j < 2; j++) wmma::fill_fragment(c[i][j], 0.0f);

    int ar = tid >> 2, ac = (tid & 3) << 3;       // A: 128 x 32
    int br = tid >> 4, bc = (tid & 15) << 3;      // B: 32 x 128

    auto load_tile = [&](int stage, int k0) {
        cp16(sA_u + (stage * AS2 + ar * 40 + ac) * 2,
             g_h1 + (size_t)(row0 + ar) * 256 + k0 + ac);
        cp16(sB_u + (stage * BS2 + br * 136 + bc) * 2,
             g_W1b + (size_t)(k0 + br) * 256 + col0 + bc);
        asm volatile("cp.async.commit_group;\n");
    };

    load_tile(0, 0);
    const int KT = 8;                             // K = 256 / 32
    for (int kt = 0; kt < KT; kt++) {
        int cur = kt & 1;
        if (kt + 1 < KT) {
            load_tile(cur ^ 1, (kt + 1) * 32);
            asm volatile("cp.async.wait_group 1;\n");
        } else {
            asm volatile("cp.async.wait_group 0;\n");
        }
        __syncthreads();
        #pragma unroll
        for (int ks = 0; ks < 2; ks++) {
            wmma::fragment<wmma::matrix_a, 16, 16, 16, bf16, wmma::row_major> a0, a1;
            wmma::fragment<wmma::matrix_b, 16, 16, 16, bf16, wmma::row_major> b0, b1;
            const bf16* pa = sA + cur * AS2 + (mw * 32) * 40 + ks * 16;
            wmma::load_matrix_sync(a0, pa, 40);
            wmma::load_matrix_sync(a1, pa + 16 * 40, 40);
            const bf16* pb = sB + cur * BS2 + (ks * 16) * 136 + nw * 32;
            wmma::load_matrix_sync(b0, pb, 136);
            wmma::load_matrix_sync(b1, pb + 16, 136);
            wmma::mma_sync(c[0][0], a0, b0, c[0][0]);
            wmma::mma_sync(c[0][1], a0, b1, c[0][1]);
            wmma::mma_sync(c[1][0], a1, b0, c[1][0]);
            wmma::mma_sync(c[1][1], a1, b1, c[1][1]);
        }
        __syncthreads();
    }

    // epilogue: per-warp private staging 32x18 floats
    float* sW = reinterpret_cast<float*>(sm) + warp * 576;
    #pragma unroll
    for (int j = 0; j < 2; j++) {
        __syncwarp();
        wmma::store_matrix_sync(sW, c[0][j], 18, wmma::mem_row_major);
        wmma::store_matrix_sync(sW + 16 * 18, c[1][j], 18, wmma::mem_row_major);
        __syncwarp();
        int r = lane;
        int grow = row0 + mw * 32 + r;
        int gcol = col0 + nw * 32 + j * 16;
        bf16* op = g_t + (size_t)grow * 256 + gcol;
        #pragma unroll
        for (int half = 0; half < 2; half++) {
            float v[8];
            #pragma unroll
            for (int q = 0; q < 8; q++)
                v[q] = gelu_tanh(sW[r * 18 + half * 8 + q] + b1[gcol + half * 8 + q]);
            __nv_bfloat162 p0 = __floats2bfloat162_rn(v[0], v[1]);
            __nv_bfloat162 p1 = __floats2bfloat162_rn(v[2], v[3]);
            __nv_bfloat162 p2 = __floats2bfloat162_rn(v[4], v[5]);
            __nv_bfloat162 p3 = __floats2bfloat162_rn(v[6], v[7]);
            uint4 u;
            u.x = *reinterpret_cast<unsigned*>(&p0);
            u.y = *reinterpret_cast<unsigned*>(&p1);
            u.z = *reinterpret_cast<unsigned*>(&p2);
            u.w = *reinterpret_cast<unsigned*>(&p3);
            *(uint4*)(op + half * 8) = u;
        }
    }
}

// ---------------- direct-WMMA GEMM (proven body), 64x128 block tile ----------------
template <int EPI, int N, int K>
__device__ __forceinline__ void gemm_body(const bf16* __restrict__ A,
                                          const bf16* __restrict__ Bw,
                                          const float* __restrict__ bias,
                                          bf16* __restrict__ Cb,
                                          float* __restrict__ Cf,
                                          const float* __restrict__ xres) {
    __shared__ float sC[64 * 132];
    int warp = threadIdx.x >> 5;
    int mw = warp >> 2, nw = warp & 3;
    int row0 = blockIdx.y * 64 + mw * 32;
    int col0 = blockIdx.x * 128 + nw * 32;

    wmma::fragment<wmma::accumulator, 16, 16, 16, float> c[2][2];
    #pragma unroll
    for (int i = 0; i < 2; i++)
        #pragma unroll
        for (int j = 0; j < 2; j++) wmma::fill_fragment(c[i][j], 0.0f);

    const bf16* Aptr = A + (size_t)row0 * K;
    #pragma unroll 4
    for (int k = 0; k < K; k += 16) {
        wmma::fragment<wmma::matrix_a, 16, 16, 16, bf16, wmma::row_major> a0, a1;
        wmma::fragment<wmma::matrix_b, 16, 16, 16, bf16, wmma::row_major> b0, b1;
        wmma::load_matrix_sync(a0, Aptr + k, K);
        wmma::load_matrix_sync(a1, Aptr + (size_t)16 * K + k, K);
        wmma::load_matrix_sync(b0, Bw + (size_t)k * N + col0, N);
        wmma::load_matrix_sync(b1, Bw + (size_t)k * N + col0 + 16, N);
        wmma::mma_sync(c[0][0], a0, b0, c[0][0]);
        wmma::mma_sync(c[0][1], a0, b1, c[0][1]);
        wmma::mma_sync(c[1][0], a1, b0, c[1][0]);
        wmma::mma_sync(c[1][1], a1, b1, c[1][1]);
    }

    #pragma unroll
    for (int i = 0; i < 2; i++)
        #pragma unroll
        for (int j = 0; j < 2; j++)
            wmma::store_matrix_sync(sC + (mw * 32 + 16 * i) * 132 + nw * 32 + 16 * j,
                                    c[i][j], 132, wmma::mem_row_major);
    __syncthreads();

    #pragma unroll
    for (int e = threadIdx.x; e < 64 * 32; e += 256) {
        int r = e >> 5;
        int c4 = (e & 31) << 2;
        int grow = blockIdx.y * 64 + r;
        int gcol = blockIdx.x * 128 + c4;
        float4 bv = *(const float4*)(bias + gcol);
        float v0 = sC[r * 132 + c4 + 0] + bv.x;
        float v1 = sC[r * 132 + c4 + 1] + bv.y;
        float v2 = sC[r * 132 + c4 + 2] + bv.z;
        float v3 = sC[r * 132 + c4 + 3] + bv.w;
        if (EPI == 2) {
            float4 xv = *(const float4*)(xres + (size_t)grow * N + gcol);
            float4 o;
            o.x = 0.5f * v0 + 0.5f * xv.x;
            o.y = 0.5f * v1 + 0.5f * xv.y;
            o.z = 0.5f * v2 + 0.5f * xv.z;
            o.w = 0.5f * v3 + 0.5f * xv.w;
            *(float4*)(Cf + (size_t)grow * N + gcol) = o;
        } else {
            __nv_bfloat162 lo = __floats2bfloat162_rn(v0, v1);
            __nv_bfloat162 hi = __floats2bfloat162_rn(v2, v3);
            uint2 u;
            u.x = *reinterpret_cast<unsigned*>(&lo);
            u.y = *reinterpret_cast<unsigned*>(&hi);
            *(uint2*)(Cb + (size_t)grow * N + gcol) = u;
        }
    }
}

__global__ void gemm3_kernel() {                                      // t@W23+b23
    gemm_body<0, 256, 256>(g_t, g_W23, g_b23, g_h3, nullptr, nullptr);
}
__global__ void gemm5_kernel(float* __restrict__ out, const float* __restrict__ x) {
    gemm_body<2, 1024, 256>(g_h3, g_Wu2, g_bu2, nullptr, out, x);     // up-proj + mix
}

// ---------------- launcher ----------------
extern "C" void kernel_launch(void* const* d_in, const int* in_sizes, int n_in,
                              void* d_out, int out_size) {
    const float* x    = (const float*)d_in[0];
    const float* ln_g = (const float*)d_in[1];
    const float* ln_b = (const float*)d_in[2];
    const float* Wd   = (const float*)d_in[3];
    const float* bd   = (const float*)d_in[4];
    const float* Wg   = (const float*)d_in[5];
    const float* bg   = (const float*)d_in[6];
    const float* dw_w = (const float*)d_in[7];
    const float* dw_b = (const float*)d_in[8];
    const float* W1   = (const float*)d_in[9];
    const float* b1   = (const float*)d_in[10];
    const float* W2   = (const float*)d_in[11];
    const float* b2   = (const float*)d_in[12];
    // d_in[13..16] = Wq,bq,Wk,bk : dead (softmax over a single key == 1)
    const float* Wv   = (const float*)d_in[17];
    const float* bv   = (const float*)d_in[18];
    const float* Wo   = (const float*)d_in[19];
    const float* bo   = (const float*)d_in[20];
    const float* Wu   = (const float*)d_in[21];
    const float* bu   = (const float*)d_in[22];
    const float* Wld  = (const float*)d_in[23];
    const float* Wlu  = (const float*)d_in[24];
    float* out = (float*)d_out;

    prep_wdg<<<(1024 * 512) / 256, 256>>>(Wd, Wg);                    // 1
    prep_bdg<<<1, 512>>>(bd, bg);                                     // 2
    ln_kernel<<<BB / 8, 256>>>(x, ln_g, ln_b);                        // 3
    gemm1_glu_kernel<<<dim3(4, BB / 64), 256>>>(dw_w, dw_b);          // 4 (ncu target)
    cvt_kernel<<<(256 * 256 + 255) / 256, 256>>>(W1, g_W1b, 256*256); // 5
    gemm2s_kernel<<<dim3(2, BB / 128), 512>>>(b1);                    // 6 (experiment)
    prep_wvo<<<256, 256>>>(Wv, Wo, bv, bo);                           // 7
    prep_w2vo<<<256, 256>>>(W2, b2);                                  // 8
    gemm3_kernel<<<dim3(2, BB / 64), 256>>>();                        // 9
    prep_T<<<256, 256>>>(Wu, Wld);                                    // 10
    prep_wu2<<<dim3(256, 4), 256>>>(Wu, Wlu);                         // 11
    prep_bu2<<<1, 1024>>>(bu, Wld, Wlu);                              // 12
    gemm5_kernel<<<dim3(8, BB / 64), 256>>>(out, x);                  // 13
}